// round 10
// baseline (speedup 1.0000x reference)
#include <cuda_runtime.h>
#include <math.h>

#define TPB 256
#define MAXK 128
#define QCAP 288

// Per-block partials: [(b*gx+bx)*4 + {stc,str,cnt,pad}]. Every used slot is
// written each run, so no zeroing kernel is needed.
__device__ float g_part[65536];
// Wrap-around completion counter: returns to 0 after every full run, so graph
// replays are deterministic without an init kernel.
__device__ unsigned g_ctr = 0;

#define C4 0.2857142857f      /* 0.4/1.4 */

__device__ __forceinline__ float softplusf(float z) {
    return fmaxf(z, 0.f) + __logf(1.f + __expf(-fabsf(z)));
}

template<int KFIX>
__global__ __launch_bounds__(TPB) void loss_kernel(
    const float* __restrict__ prop,     // (B, A, 6)
    const float* __restrict__ anchors,  // (A, 4) xywh
    const float* __restrict__ gt,       // (B, K, 4) xywh
    float* __restrict__ out,
    int A, int Krt, int totalBlocks)
{
    const int K = (KFIX > 0) ? KFIX : Krt;
    __shared__ float4 s_g[MAXK];          // gt boxes xyxy
    __shared__ float  s_ga[MAXK];         // gt areas
    __shared__ float4 s_g4v[MAXK / 4];    // 2*(2/7)*ga, packed 4-per-float4
    __shared__ int    s_q[QCAP];          // candidate anchor ids
    __shared__ int    s_qc;
    __shared__ float  r0[8], r1[8], r2[8];
    __shared__ int    s_last;
    __shared__ float  s_fin[8][4];

    const int b  = blockIdx.y;
    const int gx = gridDim.x;

    if (threadIdx.x == 0) s_qc = 0;
    for (int k = threadIdx.x; k < K; k += TPB) {
        const float* g = gt + ((size_t)b * K + k) * 4;
        float x0 = g[0], y0 = g[1], w = g[2], h = g[3];
        s_g[k]  = make_float4(x0, y0, x0 + w, y0 + h);
        float ga = w * h;
        s_ga[k] = ga;
        ((float*)s_g4v)[k] = 2.f * C4 * ga;   // doubled (screen works in 2x units)
    }
    __syncthreads();

    // ---- one anchor per thread: minimal state, max resident warps ----
    const int a = blockIdx.x * TPB + threadIdx.x;
    const int c = min(a, A - 1);

    const float4 an = reinterpret_cast<const float4*>(anchors)[c];
    const float xl  = __ldg(prop + ((size_t)b * A + c) * 6 + 4);  // logit, prefetched

    const float ax1 = an.x, ay1 = an.y;
    const float ax2 = an.x + an.z, ay2 = an.y + an.w;
    const float areaA = an.z * an.w;

    // Pipe-balanced screen, all in 2x units:
    //   M4 = max_k( 2*inter_k - 2*(2/7)*ga_k ),  2*inter = (w+|w|)*h
    //   neg  <=> M4 <  2*(2/7)*areaA     (max iou < 0.4)
    //   cand <=> M4 >= 0.6660*areaA      (superset of pos; pos => M4 >= 2*(areaA/3+ga/21))
    // (w+|w|) = 2*max(w,0) exactly; h<0 terms are <=0, harmless under max.
    // Per k: 5 alu-pipe ops (4 corner FMNMX + M4 FMNMX) + 4 fma-pipe ops
    // (2 subs + w+|w| + FFMA) -> balanced rt-2 pipes, issue ceiling ~90%.
    float M4 = -1e30f;

    if (KFIX == 64) {
#pragma unroll
        for (int k4 = 0; k4 < 16; k4++) {
            float4 gv = s_g4v[k4];
#pragma unroll
            for (int i = 0; i < 4; i++) {
                float4 g = s_g[k4 * 4 + i];
                float g4 = (i == 0) ? gv.x : (i == 1) ? gv.y : (i == 2) ? gv.z : gv.w;
                float w = fminf(ax2, g.z) - fmaxf(ax1, g.x);   // 2 alu + 1 fma
                float h = fminf(ay2, g.w) - fmaxf(ay1, g.y);   // 2 alu + 1 fma
                float wa = w + fabsf(w);                        // fma pipe, |.| free
                M4 = fmaxf(M4, fmaf(wa, h, -g4));               // 1 fma + 1 alu
            }
        }
    } else {
        for (int k = 0; k < K; k++) {
            float4 g = s_g[k];
            float g4 = ((const float*)s_g4v)[k];
            float w = fminf(ax2, g.z) - fmaxf(ax1, g.x);
            float h = fminf(ay2, g.w) - fmaxf(ay1, g.y);
            float wa = w + fabsf(w);
            M4 = fmaxf(M4, fmaf(wa, h, -g4));
        }
    }

    float stc = 0.f, strl = 0.f, cnt = 0.f;

    // classify: negatives inline, candidates to the queue
    if (a < A) {
        if (M4 < 2.f * C4 * areaA) {
            float sig = 1.f / (1.f + __expf(-xl));
            stc = 0.75f * softplusf(xl) * sig * sig;        // focal, t=0
        } else if (M4 >= 0.6660f * areaA) {
            s_q[atomicAdd(&s_qc, 1)] = a;
        }
        // else: exact-iou in [0.4, 0.5) ignore band — contributes nothing
    }
    __syncthreads();

    // ---- pass-2: exact classification + argmax for candidates (dense) ----
    const int qc = s_qc;
    for (int i = threadIdx.x; i < qc; i += TPB) {
        const int aq = s_q[i];
        const float4 aw = reinterpret_cast<const float4*>(anchors)[aq];
        const float qx1 = aw.x, qy1 = aw.y;
        const float qx2 = aw.x + aw.z, qy2 = aw.y + aw.w;
        const float qar = aw.z * aw.w;

        // division-free exact argmax (strict > keeps first max) — verified
        // path (rel_err 6.6e-8 vs reference)
        float bI = 0.f, bS = 1.f; int bK = 0;
        for (int k = 0; k < K; k++) {
            float4 g = s_g[k];
            float w = fminf(qx2, g.z) - fmaxf(qx1, g.x);
            float h = fminf(qy2, g.w) - fmaxf(qy1, g.y);
            float inter = fmaxf(w, 0.f) * h;
            float S = qar + s_ga[k];
            bool cc = inter * bS > bI * S;
            bI = cc ? inter : bI;
            bS = cc ? S : bS;
            bK = cc ? k : bK;
        }
        const float ts = bI / (bS - bI);

        const float* p = prop + ((size_t)b * A + aq) * 6;
        const float x = p[4];
        const float sig = 1.f / (1.f + __expf(-x));
        if (ts >= 0.5f) {
            cnt += 1.f;
            float om = 1.f - sig;
            stc += 0.25f * softplusf(-x) * om * om;         // focal, t=1
            float2 q01 = *reinterpret_cast<const float2*>(p);
            float2 q23 = *reinterpret_cast<const float2*>(p + 2);
            float4 g = s_g[bK];
            float ew = fmaxf(fminf(q01.x + q23.x, g.z) - fmaxf(q01.x, g.x), 0.f);
            float eh = fmaxf(fminf(q01.y + q23.y, g.w) - fmaxf(q01.y, g.y), 0.f);
            float ei = ew * eh;
            float eiou = ei / ((q23.x * q23.y + s_ga[bK]) - ei);
            strl += -__logf(eiou + 0.01f);
        } else if (ts < 0.4f) {
            stc += 0.75f * softplusf(x) * sig * sig;        // focal, t=0
        }
    }

    // ---- block reduction of (stc, strl, cnt) ----
    const unsigned m = 0xFFFFFFFFu;
#pragma unroll
    for (int o = 16; o; o >>= 1) {
        stc  += __shfl_down_sync(m, stc,  o);
        strl += __shfl_down_sync(m, strl, o);
        cnt  += __shfl_down_sync(m, cnt,  o);
    }
    const int wid = threadIdx.x >> 5, lane = threadIdx.x & 31;
    if (lane == 0) { r0[wid] = stc; r1[wid] = strl; r2[wid] = cnt; }
    __syncthreads();
    if (threadIdx.x == 0) {
        float t0 = 0.f, t1 = 0.f, t2 = 0.f;
#pragma unroll
        for (int i = 0; i < TPB / 32; i++) { t0 += r0[i]; t1 += r1[i]; t2 += r2[i]; }
        int slot = (b * gx + blockIdx.x) * 4;
        g_part[slot + 0] = t0;
        g_part[slot + 1] = t1;
        g_part[slot + 2] = t2;
        __threadfence();
        unsigned old = atomicInc(&g_ctr, (unsigned)(totalBlocks - 1));
        s_last = (old == (unsigned)(totalBlocks - 1)) ? 1 : 0;
    }
    __syncthreads();

    if (s_last) {
        const int B = gridDim.y;
        const int nwarp = TPB / 32;
        if (threadIdx.x < 32) ((float*)s_fin)[threadIdx.x] = 0.f;
        __syncthreads();

        if (B <= nwarp) {
            const int wpb = nwarp / B;            // warps per batch
            const int bb = wid / wpb;
            if (bb < B) {
                float f0 = 0.f, f1 = 0.f, f2 = 0.f;
                for (int blk = lane + 32 * (wid % wpb); blk < gx; blk += 32 * wpb) {
                    int s = (bb * gx + blk) * 4;
                    f0 += g_part[s + 0];
                    f1 += g_part[s + 1];
                    f2 += g_part[s + 2];
                }
#pragma unroll
                for (int o = 16; o; o >>= 1) {
                    f0 += __shfl_down_sync(m, f0, o);
                    f1 += __shfl_down_sync(m, f1, o);
                    f2 += __shfl_down_sync(m, f2, o);
                }
                if (lane == 0) {
                    atomicAdd(&s_fin[bb][0], f0);
                    atomicAdd(&s_fin[bb][1], f1);
                    atomicAdd(&s_fin[bb][2], f2);
                }
            }
            __syncthreads();
            if (threadIdx.x == 0) {
                float t = 0.f;
                for (int bb2 = 0; bb2 < B; bb2++) {
                    float cc = s_fin[bb2][2];
                    float safe = (cc > 0.f) ? cc : 1.f;
                    t += s_fin[bb2][0] / safe;
                    if (cc > 0.f) t += s_fin[bb2][1] / safe;
                }
                out[0] = t / (float)B;
            }
        } else if (threadIdx.x == 0) {
            // fallback (B > nwarp): serial, correctness only
            float t = 0.f;
            for (int bb2 = 0; bb2 < B; bb2++) {
                float f0 = 0.f, f1 = 0.f, f2 = 0.f;
                for (int blk = 0; blk < gx; blk++) {
                    int s = (bb2 * gx + blk) * 4;
                    f0 += g_part[s]; f1 += g_part[s + 1]; f2 += g_part[s + 2];
                }
                float safe = (f2 > 0.f) ? f2 : 1.f;
                t += f0 / safe;
                if (f2 > 0.f) t += f1 / safe;
            }
            out[0] = t / (float)B;
        }
    }
}

extern "C" void kernel_launch(void* const* d_in, const int* in_sizes, int n_in,
                              void* d_out, int out_size) {
    const float* prop    = (const float*)d_in[0];  // ss_proposal (B,A,6)
    const float* anchors = (const float*)d_in[1];  // anchors (A,4)
    const float* gt      = (const float*)d_in[2];  // ground_truth (B,K,4)

    const int A = in_sizes[1] / 4;
    const int B = in_sizes[0] / (A * 6);
    const int K = in_sizes[2] / (B * 4);

    const int gx = (A + TPB - 1) / TPB;     // 469 for A=120000
    dim3 grid(gx, B);
    const int total = gx * B;

    if (K == 64)
        loss_kernel<64><<<grid, TPB>>>(prop, anchors, gt, (float*)d_out, A, K, total);
    else
        loss_kernel<0><<<grid, TPB>>>(prop, anchors, gt, (float*)d_out, A, K, total);
}